// round 11
// baseline (speedup 1.0000x reference)
#include <cuda_runtime.h>
#include <cuda_fp16.h>

// SemiConv2d (tropical conv): out[n,oc,h,w] = max_{ic,kh,kw} min(xpad, K)
// x: (8,32,96,96) f32, K: (32,32,3,3) f32, out f32, pad=1 with -inf.
//
// Per-(oc,kw) sorted tap lists (desc k), round-robin with one exact exit
// check per iteration (vs max of the 3 heads). 32-bit records + 384-thread
// blocks (16 w-cols/thread) -> 75.7 KB smem -> 3 blocks/SM -> all 384
// blocks co-resident (single wave, no tail).

#define N_      8
#define IC_     32
#define OC_     32
#define H_      96
#define W_      96
#define TILE_H  8
#define XROWS   10           // TILE_H + 2 halo
#define XS_STRIDE 104        // halves per row (208 B, 16B multiple)
#define OC_PER_BLK 8
#define THREADS 384
#define NTAPS   288
#define LTAPS   96           // taps per (oc, kw) list

// rec = k_half_bits << 16 | (row_byte_offset >> 4)   (offset is 16B multiple)
__device__ unsigned g_taps[OC_ * 3 * LTAPS];

__global__ void semiconv2d_prep(const float* __restrict__ kern) {
    __shared__ __half kv[3][LTAPS];
    const int oc = blockIdx.x;
    const int t  = threadIdx.x;
    int ic = t / 9, rr = t % 9, kh = rr / 3, kw = rr % 3;
    int li = ic * 3 + kh;
    __half me = __float2half_rn(kern[oc * NTAPS + t]);
    kv[kw][li] = me;
    __syncthreads();
    int rank = 0;
    #pragma unroll 4
    for (int j = 0; j < LTAPS; j++) {
        __half kj = kv[kw][j];
        rank += (__hgt(kj, me) || (__heq(kj, me) && j < li)) ? 1 : 0;
    }
    unsigned bits = (unsigned)__half_as_ushort(me);
    unsigned offb = (unsigned)(((ic * XROWS + kh) * XS_STRIDE) * 2);   // bytes, 16B mult
    g_taps[(oc * 3 + kw) * LTAPS + rank] = (bits << 16) | (offb >> 4);
}

__device__ __forceinline__ __half2 u2h2(unsigned u) { return *(__half2*)&u; }

__global__ __launch_bounds__(THREADS, 3)
void semiconv2d_rr16(const float* __restrict__ x,
                     float* __restrict__ out) {
    extern __shared__ __align__(16) char smraw[];
    __half*   xs    = (__half*)smraw;                                 // [IC][XROWS][XS_STRIDE]
    unsigned* tapss = (unsigned*)(smraw + (size_t)IC_ * XROWS * XS_STRIDE * sizeof(__half));

    const int tid    = threadIdx.x;
    const int n      = blockIdx.z;
    const int ocbase = blockIdx.y * OC_PER_BLK;
    const int h0     = blockIdx.x * TILE_H;
    const __half2 NEG2 = __half2half2(__ushort_as_half((unsigned short)0xFC00));
    const float   NEGF = -__int_as_float(0x7f800000);

    // ---- fill x tile: one row per thread (320 rows), -inf halo ----
    const float* xn = x + (size_t)n * IC_ * H_ * W_;
    if (tid < IC_ * XROWS) {
        int ic = tid / XROWS, r = tid % XROWS;
        int g  = h0 - 1 + r;
        __half2* dst = (__half2*)(xs + tid * XS_STRIDE);
        if (g >= 0 && g < H_) {
            const float* xr = xn + (ic * H_ + g) * W_;
            dst[0] = __floats2half2_rn(NEGF, xr[0]);                  // cols 0,1
            #pragma unroll 4
            for (int c2 = 1; c2 < 48; c2++)                           // cols 2..95
                dst[c2] = __floats2half2_rn(xr[2 * c2 - 1], xr[2 * c2]);
            dst[48] = __floats2half2_rn(xr[95], NEGF);                // cols 96,97
            dst[49] = NEG2; dst[50] = NEG2; dst[51] = NEG2;
        } else {
            #pragma unroll 4
            for (int c2 = 0; c2 < 52; c2++) dst[c2] = NEG2;
        }
    }
    // ---- sorted tap lists for this block's 8 ocs ----
    {
        const uint4* src = (const uint4*)(g_taps + (size_t)ocbase * 3 * LTAPS);
        uint4*       dst = (uint4*)tapss;
        for (int e = tid; e < OC_PER_BLK * 3 * LTAPS / 4; e += THREADS)
            dst[e] = src[e];
    }
    __syncthreads();

    // thread -> (local oc, h row, 16-wide w strip); warp is oc-uniform (48 thr/oc)
    const int ocl = tid / 48;
    const int s   = tid % 48;
    const int hl  = s / 6;              // 0..7
    const int w0  = (s % 6) * 16;       // 0,16,..,80 (32B offsets)
    const int h   = h0 + hl;

    __half2 acc0 = NEG2, acc1 = NEG2, acc2 = NEG2, acc3 = NEG2;
    __half2 acc4 = NEG2, acc5 = NEG2, acc6 = NEG2, acc7 = NEG2;

    const char*     xb  = (const char*)(xs + hl * XS_STRIDE + w0);   // 16B aligned
    const unsigned* tp0 = tapss + ocl * 3 * LTAPS;
    const unsigned* tp1 = tp0 + LTAPS;
    const unsigned* tp2 = tp0 + 2 * LTAPS;

    #pragma unroll 1
    for (int i = 0; i < LTAPS; i += 2) {
        uint2 r0 = *(const uint2*)(tp0 + i);    // 2 recs kw=0
        uint2 r1 = *(const uint2*)(tp1 + i);    // 2 recs kw=1
        uint2 r2 = *(const uint2*)(tp2 + i);    // 2 recs kw=2

        // exact exit vs max of the 3 list heads
        unsigned kh0 = __byte_perm(r0.x, r0.x, 0x3232);
        unsigned kh1 = __byte_perm(r1.x, r1.x, 0x3232);
        unsigned kh2 = __byte_perm(r2.x, r2.x, 0x3232);
        __half2 kmax = __hmax2(__hmax2(u2h2(kh0), u2h2(kh1)), u2h2(kh2));
        __half2 m = __hmin2(__hmin2(__hmin2(acc0, acc1), __hmin2(acc2, acc3)),
                            __hmin2(__hmin2(acc4, acc5), __hmin2(acc6, acc7)));
        if (__hbge2(m, kmax)) break;

        // ---- kw = 0 (x2): cols w0..w0+15 ----
        #pragma unroll
        for (int j = 0; j < 2; j++) {
            unsigned rec = j ? r0.y : r0.x;
            const char* row = xb + ((rec & 0xffffu) << 4);
            uint4 va = *(const uint4*)row;
            uint4 vb = *(const uint4*)(row + 16);
            unsigned ku = __byte_perm(rec, rec, 0x3232);
            __half2 k = u2h2(ku);
            acc0 = __hmax2(acc0, __hmin2(u2h2(va.x), k));
            acc1 = __hmax2(acc1, __hmin2(u2h2(va.y), k));
            acc2 = __hmax2(acc2, __hmin2(u2h2(va.z), k));
            acc3 = __hmax2(acc3, __hmin2(u2h2(va.w), k));
            acc4 = __hmax2(acc4, __hmin2(u2h2(vb.x), k));
            acc5 = __hmax2(acc5, __hmin2(u2h2(vb.y), k));
            acc6 = __hmax2(acc6, __hmin2(u2h2(vb.z), k));
            acc7 = __hmax2(acc7, __hmin2(u2h2(vb.w), k));
        }
        // ---- kw = 1 (x2): cols w0+1..w0+16 via PRMT 0x5432 ----
        #pragma unroll
        for (int j = 0; j < 2; j++) {
            unsigned rec = j ? r1.y : r1.x;
            const char* row = xb + ((rec & 0xffffu) << 4);
            uint4 va = *(const uint4*)row;
            uint4 vb = *(const uint4*)(row + 16);
            unsigned ve = *(const unsigned*)(row + 32);
            unsigned ku = __byte_perm(rec, rec, 0x3232);
            __half2 k = u2h2(ku);
            acc0 = __hmax2(acc0, __hmin2(u2h2(__byte_perm(va.x, va.y, 0x5432)), k));
            acc1 = __hmax2(acc1, __hmin2(u2h2(__byte_perm(va.y, va.z, 0x5432)), k));
            acc2 = __hmax2(acc2, __hmin2(u2h2(__byte_perm(va.z, va.w, 0x5432)), k));
            acc3 = __hmax2(acc3, __hmin2(u2h2(__byte_perm(va.w, vb.x, 0x5432)), k));
            acc4 = __hmax2(acc4, __hmin2(u2h2(__byte_perm(vb.x, vb.y, 0x5432)), k));
            acc5 = __hmax2(acc5, __hmin2(u2h2(__byte_perm(vb.y, vb.z, 0x5432)), k));
            acc6 = __hmax2(acc6, __hmin2(u2h2(__byte_perm(vb.z, vb.w, 0x5432)), k));
            acc7 = __hmax2(acc7, __hmin2(u2h2(__byte_perm(vb.w, ve,   0x5432)), k));
        }
        // ---- kw = 2 (x2): cols w0+2..w0+17, pure register select ----
        #pragma unroll
        for (int j = 0; j < 2; j++) {
            unsigned rec = j ? r2.y : r2.x;
            const char* row = xb + ((rec & 0xffffu) << 4);
            uint4 va = *(const uint4*)row;
            uint4 vb = *(const uint4*)(row + 16);
            unsigned ve = *(const unsigned*)(row + 32);
            unsigned ku = __byte_perm(rec, rec, 0x3232);
            __half2 k = u2h2(ku);
            acc0 = __hmax2(acc0, __hmin2(u2h2(va.y), k));
            acc1 = __hmax2(acc1, __hmin2(u2h2(va.z), k));
            acc2 = __hmax2(acc2, __hmin2(u2h2(va.w), k));
            acc3 = __hmax2(acc3, __hmin2(u2h2(vb.x), k));
            acc4 = __hmax2(acc4, __hmin2(u2h2(vb.y), k));
            acc5 = __hmax2(acc5, __hmin2(u2h2(vb.z), k));
            acc6 = __hmax2(acc6, __hmin2(u2h2(vb.w), k));
            acc7 = __hmax2(acc7, __hmin2(u2h2(ve),   k));
        }
    }

    // ---- write 16 w outputs as f32 ----
    int oc = ocbase + ocl;
    float4* o = (float4*)(out + (((size_t)n * OC_ + oc) * H_ + h) * W_ + w0);
    float2 f0 = __half22float2(acc0), f1 = __half22float2(acc1);
    float2 f2 = __half22float2(acc2), f3 = __half22float2(acc3);
    float2 f4 = __half22float2(acc4), f5 = __half22float2(acc5);
    float2 f6 = __half22float2(acc6), f7 = __half22float2(acc7);
    o[0] = make_float4(f0.x, f0.y, f1.x, f1.y);
    o[1] = make_float4(f2.x, f2.y, f3.x, f3.y);
    o[2] = make_float4(f4.x, f4.y, f5.x, f5.y);
    o[3] = make_float4(f6.x, f6.y, f7.x, f7.y);
}

extern "C" void kernel_launch(void* const* d_in, const int* in_sizes, int n_in,
                              void* d_out, int out_size) {
    const float* x = (const float*)d_in[0];
    const float* k = (const float*)d_in[1];
    float* out = (float*)d_out;

    semiconv2d_prep<<<OC_, NTAPS>>>(k);

    size_t smem = (size_t)IC_ * XROWS * XS_STRIDE * sizeof(__half)
                + (size_t)OC_PER_BLK * 3 * LTAPS * sizeof(unsigned); // 66560 + 9216 = 75776
    cudaFuncSetAttribute(semiconv2d_rr16,
                         cudaFuncAttributeMaxDynamicSharedMemorySize, (int)smem);
    dim3 grid(H_ / TILE_H, OC_ / OC_PER_BLK, N_);                    // 12 x 4 x 8 = 384
    semiconv2d_rr16<<<grid, THREADS, smem>>>(x, out);
}

// round 12
// speedup vs baseline: 1.6259x; 1.6259x over previous
#include <cuda_runtime.h>
#include <cuda_fp16.h>

// SemiConv2d (tropical conv): out[n,oc,h,w] = max_{ic,kh,kw} min(xpad, K)
// x: (8,32,96,96) f32, K: (32,32,3,3) f32, out f32, pad=1 with -inf.
//
// Round-robin over per-(oc,kw) sorted tap lists (desc k), one exact exit
// check per iteration vs max of the 3 list heads. R10 datapath (4 accs,
// 8-wide, no spills) with OC_PER_BLK=4 / 384 threads -> 71 KB smem ->
// 3 blocks/SM -> 768-block grid at 86.5% wave utilization.

#define N_      8
#define IC_     32
#define OC_     32
#define H_      96
#define W_      96
#define TILE_H  8
#define XROWS   10           // TILE_H + 2 halo
#define XS_STRIDE 104        // halves per row (208 B, 16B multiple)
#define OC_PER_BLK 4
#define THREADS 384
#define NTAPS   288
#define LTAPS   96           // taps per (oc, kw) list

// rec = k_half_bits << 16 | (row_byte_offset >> 4)
__device__ unsigned g_taps[OC_ * 3 * LTAPS];

__global__ void semiconv2d_prep(const float* __restrict__ kern) {
    __shared__ __half kv[3][LTAPS];
    const int oc = blockIdx.x;
    const int t  = threadIdx.x;
    int ic = t / 9, rr = t % 9, kh = rr / 3, kw = rr % 3;
    int li = ic * 3 + kh;
    __half me = __float2half_rn(kern[oc * NTAPS + t]);
    kv[kw][li] = me;
    __syncthreads();
    int rank = 0;
    #pragma unroll 4
    for (int j = 0; j < LTAPS; j++) {
        __half kj = kv[kw][j];
        rank += (__hgt(kj, me) || (__heq(kj, me) && j < li)) ? 1 : 0;
    }
    unsigned bits = (unsigned)__half_as_ushort(me);
    unsigned offb = (unsigned)(((ic * XROWS + kh) * XS_STRIDE) * 2);   // bytes, 16B mult
    g_taps[(oc * 3 + kw) * LTAPS + rank] = (bits << 16) | (offb >> 4);
}

__device__ __forceinline__ __half2 u2h2(unsigned u) { return *(__half2*)&u; }

__global__ __launch_bounds__(THREADS, 3)
void semiconv2d_rr4(const float* __restrict__ x,
                    float* __restrict__ out) {
    extern __shared__ __align__(16) char smraw[];
    __half*   xs    = (__half*)smraw;                                 // [IC][XROWS][XS_STRIDE]
    unsigned* tapss = (unsigned*)(smraw + (size_t)IC_ * XROWS * XS_STRIDE * sizeof(__half));

    const int tid    = threadIdx.x;
    const int n      = blockIdx.z;
    const int ocbase = blockIdx.y * OC_PER_BLK;
    const int h0     = blockIdx.x * TILE_H;
    const float   NEGF = -__int_as_float(0x7f800000);
    const __half2 NEG2 = __half2half2(__ushort_as_half((unsigned short)0xFC00));

    // ---- fill x tile (half2 granularity, -inf halo) ----
    const float* xn = x + (size_t)n * IC_ * H_ * W_;
    __half2* xsh2 = (__half2*)xs;
    const int NH2 = IC_ * XROWS * (XS_STRIDE / 2);
    for (int t = tid; t < NH2; t += THREADS) {
        int row = t / (XS_STRIDE / 2);
        int c2  = t % (XS_STRIDE / 2);
        int ic  = row / XROWS;
        int r   = row % XROWS;
        int g   = h0 - 1 + r;
        int p0  = 2 * c2;
        float a = NEGF, b = NEGF;
        if (g >= 0 && g < H_) {
            const float* xr = xn + (ic * H_ + g) * W_;
            if (p0 >= 1 && p0 <= W_)         a = xr[p0 - 1];
            if (p0 + 1 >= 1 && p0 + 1 <= W_) b = xr[p0];
        }
        xsh2[t] = __floats2half2_rn(a, b);
    }
    // ---- sorted tap lists for this block's 4 ocs ----
    {
        const uint4* src = (const uint4*)(g_taps + (size_t)ocbase * 3 * LTAPS);
        uint4*       dst = (uint4*)tapss;
        for (int e = tid; e < OC_PER_BLK * 3 * LTAPS / 4; e += THREADS)
            dst[e] = src[e];
    }
    __syncthreads();

    // thread -> (local oc, h row, 8-wide w strip); warp is oc-uniform
    const int ocl = tid / 96;           // 0..3
    const int s   = tid % 96;
    const int hl  = s / 12;
    const int w0  = (s % 12) * 8;
    const int h   = h0 + hl;

    __half2 acc0 = NEG2, acc1 = NEG2, acc2 = NEG2, acc3 = NEG2;

    const char*     xb  = (const char*)(xs + hl * XS_STRIDE + w0);   // 16B aligned
    const unsigned* tp0 = tapss + ocl * 3 * LTAPS;
    const unsigned* tp1 = tp0 + LTAPS;
    const unsigned* tp2 = tp0 + 2 * LTAPS;

    #pragma unroll 1
    for (int i = 0; i < LTAPS; i += 2) {
        uint2 r0 = *(const uint2*)(tp0 + i);
        uint2 r1 = *(const uint2*)(tp1 + i);
        uint2 r2 = *(const uint2*)(tp2 + i);

        // exact exit: every remaining tap has k <= max of the 3 heads
        unsigned kh0 = __byte_perm(r0.x, r0.x, 0x3232);
        unsigned kh1 = __byte_perm(r1.x, r1.x, 0x3232);
        unsigned kh2 = __byte_perm(r2.x, r2.x, 0x3232);
        __half2 kmax = __hmax2(__hmax2(u2h2(kh0), u2h2(kh1)), u2h2(kh2));
        __half2 m    = __hmin2(__hmin2(acc0, acc1), __hmin2(acc2, acc3));
        if (__hbge2(m, kmax)) break;

        // ---- kw = 0 (x2): cols w0..w0+7 = va.x..va.w ----
        #pragma unroll
        for (int j = 0; j < 2; j++) {
            unsigned rec = j ? r0.y : r0.x;
            uint4 va = *(const uint4*)(xb + ((rec & 0xffffu) << 4));
            __half2 k = u2h2(__byte_perm(rec, rec, 0x3232));
            acc0 = __hmax2(acc0, __hmin2(u2h2(va.x), k));
            acc1 = __hmax2(acc1, __hmin2(u2h2(va.y), k));
            acc2 = __hmax2(acc2, __hmin2(u2h2(va.z), k));
            acc3 = __hmax2(acc3, __hmin2(u2h2(va.w), k));
        }
        // ---- kw = 1 (x2): cols w0+1..w0+8 via PRMT 0x5432 ----
        #pragma unroll
        for (int j = 0; j < 2; j++) {
            unsigned rec = j ? r1.y : r1.x;
            const char* row = xb + ((rec & 0xffffu) << 4);
            uint4 va = *(const uint4*)row;
            unsigned ve = *(const unsigned*)(row + 16);
            __half2 k = u2h2(__byte_perm(rec, rec, 0x3232));
            acc0 = __hmax2(acc0, __hmin2(u2h2(__byte_perm(va.x, va.y, 0x5432)), k));
            acc1 = __hmax2(acc1, __hmin2(u2h2(__byte_perm(va.y, va.z, 0x5432)), k));
            acc2 = __hmax2(acc2, __hmin2(u2h2(__byte_perm(va.z, va.w, 0x5432)), k));
            acc3 = __hmax2(acc3, __hmin2(u2h2(__byte_perm(va.w, ve,   0x5432)), k));
        }
        // ---- kw = 2 (x2): cols w0+2..w0+9, pure register select ----
        #pragma unroll
        for (int j = 0; j < 2; j++) {
            unsigned rec = j ? r2.y : r2.x;
            const char* row = xb + ((rec & 0xffffu) << 4);
            uint4 va = *(const uint4*)row;
            unsigned ve = *(const unsigned*)(row + 16);
            __half2 k = u2h2(__byte_perm(rec, rec, 0x3232));
            acc0 = __hmax2(acc0, __hmin2(u2h2(va.y), k));
            acc1 = __hmax2(acc1, __hmin2(u2h2(va.z), k));
            acc2 = __hmax2(acc2, __hmin2(u2h2(va.w), k));
            acc3 = __hmax2(acc3, __hmin2(u2h2(ve),   k));
        }
    }

    // ---- write 8 w outputs as f32 ----
    int oc = ocbase + ocl;
    float4* o = (float4*)(out + (((size_t)n * OC_ + oc) * H_ + h) * W_ + w0);
    float2 f0 = __half22float2(acc0);
    float2 f1 = __half22float2(acc1);
    float2 f2 = __half22float2(acc2);
    float2 f3 = __half22float2(acc3);
    o[0] = make_float4(f0.x, f0.y, f1.x, f1.y);
    o[1] = make_float4(f2.x, f2.y, f3.x, f3.y);
}

extern "C" void kernel_launch(void* const* d_in, const int* in_sizes, int n_in,
                              void* d_out, int out_size) {
    const float* x = (const float*)d_in[0];
    const float* k = (const float*)d_in[1];
    float* out = (float*)d_out;

    semiconv2d_prep<<<OC_, NTAPS>>>(k);

    size_t smem = (size_t)IC_ * XROWS * XS_STRIDE * sizeof(__half)
                + (size_t)OC_PER_BLK * 3 * LTAPS * sizeof(unsigned); // 66560 + 4608 = 71168
    cudaFuncSetAttribute(semiconv2d_rr4,
                         cudaFuncAttributeMaxDynamicSharedMemorySize, (int)smem);
    dim3 grid(H_ / TILE_H, OC_ / OC_PER_BLK, N_);                    // 12 x 8 x 8 = 768
    semiconv2d_rr4<<<grid, THREADS, smem>>>(x, out);
}

// round 13
// speedup vs baseline: 1.8634x; 1.1461x over previous
#include <cuda_runtime.h>
#include <cuda_fp16.h>

// SemiConv2d (tropical conv): out[n,oc,h,w] = max_{ic,kh,kw} min(xpad, K)
// x: (8,32,96,96) f32, K: (32,32,3,3) f32, out f32, pad=1 with -inf.
//
// R10 datapath with a WARP-UNIFORM early exit: since issue cost is per-warp
// (predicated-off lanes still issue), per-thread breaks only add divergence
// overhead. __all_sync vote -> uniform branch, zero divergence machinery.

#define N_      8
#define IC_     32
#define OC_     32
#define H_      96
#define W_      96
#define TILE_H  8
#define XROWS   10           // TILE_H + 2 halo
#define XS_STRIDE 104        // halves per row (208 B, 16B multiple)
#define OC_PER_BLK 8
#define THREADS 768
#define NTAPS   288
#define LTAPS   96           // taps per (oc, kw) list

__device__ uint2 g_taps[OC_ * 3 * LTAPS];   // [oc][kw][rank] = (k_splat, byte_off)

__global__ void semiconv2d_prep(const float* __restrict__ kern) {
    __shared__ __half kv[3][LTAPS];
    const int oc = blockIdx.x;
    const int t  = threadIdx.x;
    int ic = t / 9, rr = t % 9, kh = rr / 3, kw = rr % 3;
    int li = ic * 3 + kh;
    __half me = __float2half_rn(kern[oc * NTAPS + t]);
    kv[kw][li] = me;
    __syncthreads();
    int rank = 0;
    #pragma unroll 4
    for (int j = 0; j < LTAPS; j++) {
        __half kj = kv[kw][j];
        rank += (__hgt(kj, me) || (__heq(kj, me) && j < li)) ? 1 : 0;
    }
    unsigned bits = (unsigned)__half_as_ushort(me);
    unsigned kspl = bits * 0x10001u;
    unsigned offb = (unsigned)(((ic * XROWS + kh) * XS_STRIDE) * 2);   // bytes
    g_taps[(oc * 3 + kw) * LTAPS + rank] = make_uint2(kspl, offb);
}

__device__ __forceinline__ __half2 u2h2(unsigned u) { return *(__half2*)&u; }

__global__ __launch_bounds__(THREADS, 2)
void semiconv2d_rrw(const float* __restrict__ x,
                    float* __restrict__ out) {
    extern __shared__ __align__(16) char smraw[];
    __half* xs    = (__half*)smraw;                                 // [IC][XROWS][XS_STRIDE]
    uint2*  tapss = (uint2*)(smraw + (size_t)IC_ * XROWS * XS_STRIDE * sizeof(__half));

    const int tid    = threadIdx.x;
    const int n      = blockIdx.z;
    const int ocbase = blockIdx.y * OC_PER_BLK;
    const int h0     = blockIdx.x * TILE_H;
    const float   NEGF = -__int_as_float(0x7f800000);
    const __half2 NEG2 = __half2half2(__ushort_as_half((unsigned short)0xFC00));

    // ---- fill x tile (half2 granularity, -inf halo) ----
    const float* xn = x + (size_t)n * IC_ * H_ * W_;
    __half2* xsh2 = (__half2*)xs;
    const int NH2 = IC_ * XROWS * (XS_STRIDE / 2);
    for (int t = tid; t < NH2; t += THREADS) {
        int row = t / (XS_STRIDE / 2);
        int c2  = t % (XS_STRIDE / 2);
        int ic  = row / XROWS;
        int r   = row % XROWS;
        int g   = h0 - 1 + r;
        int p0  = 2 * c2;
        float a = NEGF, b = NEGF;
        if (g >= 0 && g < H_) {
            const float* xr = xn + (ic * H_ + g) * W_;
            if (p0 >= 1 && p0 <= W_)         a = xr[p0 - 1];
            if (p0 + 1 >= 1 && p0 + 1 <= W_) b = xr[p0];
        }
        xsh2[t] = __floats2half2_rn(a, b);
    }
    {
        const uint4* src = (const uint4*)(g_taps + (size_t)ocbase * 3 * LTAPS);
        uint4*       dst = (uint4*)tapss;
        for (int e = tid; e < OC_PER_BLK * 3 * LTAPS / 2; e += THREADS)
            dst[e] = src[e];
    }
    __syncthreads();

    // thread -> (local oc, h row, 8-wide w strip); warp is oc-uniform
    const int ocl = tid / 96;
    const int s   = tid % 96;
    const int hl  = s / 12;
    const int w0  = (s % 12) * 8;
    const int h   = h0 + hl;

    __half2 acc0 = NEG2, acc1 = NEG2, acc2 = NEG2, acc3 = NEG2;

    const char*  xb  = (const char*)(xs + hl * XS_STRIDE + w0);   // 16B aligned base
    const uint2* tp0 = tapss + ocl * 3 * LTAPS;
    const uint2* tp1 = tp0 + LTAPS;
    const uint2* tp2 = tp0 + 2 * LTAPS;

    #pragma unroll 1
    for (int i = 0; i < LTAPS; i += 2) {
        uint4 r0 = *(const uint4*)(tp0 + i);    // 2 recs, kw=0
        uint4 r1 = *(const uint4*)(tp1 + i);    // 2 recs, kw=1
        uint4 r2 = *(const uint4*)(tp2 + i);    // 2 recs, kw=2

        // warp-uniform exact exit: all lanes done -> whole warp breaks.
        // (Per-lane exit saves no issue slots; it only adds divergence.)
        __half2 kmax = __hmax2(__hmax2(u2h2(r0.x), u2h2(r1.x)), u2h2(r2.x));
        __half2 m    = __hmin2(__hmin2(acc0, acc1), __hmin2(acc2, acc3));
        if (__all_sync(0xffffffffu, __hbge2(m, kmax))) break;

        // ---- kw = 0: cols w0..w0+7 = va.x..va.w ----
        {
            uint4 va = *(const uint4*)(xb + r0.y); __half2 k = u2h2(r0.x);
            acc0 = __hmax2(acc0, __hmin2(u2h2(va.x), k));
            acc1 = __hmax2(acc1, __hmin2(u2h2(va.y), k));
            acc2 = __hmax2(acc2, __hmin2(u2h2(va.z), k));
            acc3 = __hmax2(acc3, __hmin2(u2h2(va.w), k));
        }
        {
            uint4 va = *(const uint4*)(xb + r0.w); __half2 k = u2h2(r0.z);
            acc0 = __hmax2(acc0, __hmin2(u2h2(va.x), k));
            acc1 = __hmax2(acc1, __hmin2(u2h2(va.y), k));
            acc2 = __hmax2(acc2, __hmin2(u2h2(va.z), k));
            acc3 = __hmax2(acc3, __hmin2(u2h2(va.w), k));
        }
        // ---- kw = 1: cols w0+1..w0+8 via PRMT 0x5432 ----
        {
            uint4 va = *(const uint4*)(xb + r1.y);
            unsigned ve = *(const unsigned*)(xb + r1.y + 16);
            __half2 k = u2h2(r1.x);
            acc0 = __hmax2(acc0, __hmin2(u2h2(__byte_perm(va.x, va.y, 0x5432)), k));
            acc1 = __hmax2(acc1, __hmin2(u2h2(__byte_perm(va.y, va.z, 0x5432)), k));
            acc2 = __hmax2(acc2, __hmin2(u2h2(__byte_perm(va.z, va.w, 0x5432)), k));
            acc3 = __hmax2(acc3, __hmin2(u2h2(__byte_perm(va.w, ve,   0x5432)), k));
        }
        {
            uint4 va = *(const uint4*)(xb + r1.w);
            unsigned ve = *(const unsigned*)(xb + r1.w + 16);
            __half2 k = u2h2(r1.z);
            acc0 = __hmax2(acc0, __hmin2(u2h2(__byte_perm(va.x, va.y, 0x5432)), k));
            acc1 = __hmax2(acc1, __hmin2(u2h2(__byte_perm(va.y, va.z, 0x5432)), k));
            acc2 = __hmax2(acc2, __hmin2(u2h2(__byte_perm(va.z, va.w, 0x5432)), k));
            acc3 = __hmax2(acc3, __hmin2(u2h2(__byte_perm(va.w, ve,   0x5432)), k));
        }
        // ---- kw = 2: cols w0+2..w0+9 = va.y..va.w, ve ----
        {
            uint4 va = *(const uint4*)(xb + r2.y);
            unsigned ve = *(const unsigned*)(xb + r2.y + 16);
            __half2 k = u2h2(r2.x);
            acc0 = __hmax2(acc0, __hmin2(u2h2(va.y), k));
            acc1 = __hmax2(acc1, __hmin2(u2h2(va.z), k));
            acc2 = __hmax2(acc2, __hmin2(u2h2(va.w), k));
            acc3 = __hmax2(acc3, __hmin2(u2h2(ve),   k));
        }
        {
            uint4 va = *(const uint4*)(xb + r2.w);
            unsigned ve = *(const unsigned*)(xb + r2.w + 16);
            __half2 k = u2h2(r2.z);
            acc0 = __hmax2(acc0, __hmin2(u2h2(va.y), k));
            acc1 = __hmax2(acc1, __hmin2(u2h2(va.z), k));
            acc2 = __hmax2(acc2, __hmin2(u2h2(va.w), k));
            acc3 = __hmax2(acc3, __hmin2(u2h2(ve),   k));
        }
    }

    // ---- write 8 w outputs as f32 ----
    int oc = ocbase + ocl;
    float4* o = (float4*)(out + (((size_t)n * OC_ + oc) * H_ + h) * W_ + w0);
    float2 f0 = __half22float2(acc0);
    float2 f1 = __half22float2(acc1);
    float2 f2 = __half22float2(acc2);
    float2 f3 = __half22float2(acc3);
    o[0] = make_float4(f0.x, f0.y, f1.x, f1.y);
    o[1] = make_float4(f2.x, f2.y, f3.x, f3.y);
}

extern "C" void kernel_launch(void* const* d_in, const int* in_sizes, int n_in,
                              void* d_out, int out_size) {
    const float* x = (const float*)d_in[0];
    const float* k = (const float*)d_in[1];
    float* out = (float*)d_out;

    semiconv2d_prep<<<OC_, NTAPS>>>(k);

    size_t smem = (size_t)IC_ * XROWS * XS_STRIDE * sizeof(__half)
                + (size_t)OC_PER_BLK * 3 * LTAPS * sizeof(uint2);  // 66560 + 18432 = 84992
    cudaFuncSetAttribute(semiconv2d_rrw,
                         cudaFuncAttributeMaxDynamicSharedMemorySize, (int)smem);
    dim3 grid(H_ / TILE_H, OC_ / OC_PER_BLK, N_);                   // 12 x 4 x 8 = 384
    semiconv2d_rrw<<<grid, THREADS, smem>>>(x, out);
}